// round 4
// baseline (speedup 1.0000x reference)
#include <cuda_runtime.h>
#include <cuda_bf16.h>
#include <math.h>
#include <stdint.h>

#define Nn 65536
#define Dd 1024
#define Ss 512
#define Kslots 64
#define AGG_BLOCKS 256
#define AGG_ROWS (Nn / AGG_BLOCKS)

typedef __nv_bfloat16 bf16;

// ======================= helpers =============================================
__device__ __forceinline__ uint32_t smem_u32(const void* p) {
    uint32_t a;
    asm("{ .reg .u64 t; cvta.to.shared.u64 t, %1; cvt.u32.u64 %0, t; }" : "=r"(a) : "l"(p));
    return a;
}
__device__ __forceinline__ void cp16(uint32_t dst, const void* src) {
    asm volatile("cp.async.cg.shared.global [%0], [%1], 16;" :: "r"(dst), "l"(src));
}
__device__ __forceinline__ void ldsm4(uint32_t* r, uint32_t addr) {
    asm volatile("ldmatrix.sync.aligned.m8n8.x4.shared.b16 {%0,%1,%2,%3}, [%4];"
                 : "=r"(r[0]), "=r"(r[1]), "=r"(r[2]), "=r"(r[3]) : "r"(addr));
}
__device__ __forceinline__ void hmma(float* c, const uint32_t* a, const uint32_t* b) {
    asm volatile(
        "mma.sync.aligned.m16n8k16.row.col.f32.bf16.bf16.f32 "
        "{%0,%1,%2,%3}, {%4,%5,%6,%7}, {%8,%9}, {%0,%1,%2,%3};"
        : "+f"(c[0]), "+f"(c[1]), "+f"(c[2]), "+f"(c[3])
        : "r"(a[0]), "r"(a[1]), "r"(a[2]), "r"(a[3]), "r"(b[0]), "r"(b[1]));
}
__device__ __forceinline__ void split2(float x, bf16& h, bf16& l) {
    h = __float2bfloat16(x);
    l = __float2bfloat16(x - __bfloat162float(h));
}

// ======================= device global scratch ===============================
__device__ __align__(1024) bf16 g_xh[(size_t)Nn * Dd], g_xl[(size_t)Nn * Dd];
__device__ __align__(1024) bf16 g_qh[(size_t)Nn * Ss], g_ql[(size_t)Nn * Ss];
__device__ __align__(1024) bf16 g_ath[(size_t)Nn * Kslots], g_atl[(size_t)Nn * Kslots];
__device__ __align__(1024) bf16 g_rh[(size_t)Nn * Ss], g_rl[(size_t)Nn * Ss];
__device__ __align__(1024) bf16 g_hh[(size_t)Nn * Dd], g_hl[(size_t)Nn * Dd];
__device__ __align__(1024) float g_ro[(size_t)Nn * Dd];
__device__ __align__(1024) float g_logits[(size_t)Nn * Kslots];
__device__ __align__(1024) float g_erase[(size_t)Nn * Ss];
__device__ __align__(1024) float g_content[(size_t)Nn * Ss];
__device__ __align__(1024) float g_weighted[(size_t)Nn * Kslots];
__device__ float g_gate[Nn];
__device__ __align__(1024) float g_partE[(size_t)AGG_BLOCKS * Kslots * Ss];
__device__ __align__(1024) float g_partW[(size_t)AGG_BLOCKS * Kslots * Ss];
// weights transposed to [n,k] K-major, bf16 hi/lo planes
__device__ __align__(1024) bf16 g_wqT[2][(size_t)Ss * Dd];
__device__ __align__(1024) bf16 g_woT[2][(size_t)Dd * Ss];
__device__ __align__(1024) bf16 g_wall[2][(size_t)(3 * Ss) * Dd];  // [Wa;We;Wc]^T
__device__ __align__(1024) bf16 g_kp[2][(size_t)Kslots * Ss];      // Kp  [64,512]
__device__ __align__(1024) bf16 g_vT[2][(size_t)Ss * Kslots];      // V^T [512,64]
__device__ __align__(1024) bf16 g_st[2][(size_t)Kslots * Ss];      // state [64,512]

// ======================= mma.sync bf16 split GEMM ============================
// C[M,Nc] = act( (Ah+Al) @ (Bh+Bl)^T );  A,B stored [rows,K] K-major.
// 3-term: Ah*Bh + Ah*Bl + Al*Bh, fp32 accumulate in registers.
// MODE: 0 fp32, 1 fp32*scale, 4 split bf16 out,
//       5 fused-triple (cols [0,512): split bf16 -> Chi/Clo,
//                       [512,1024): sigmoid(+bias) -> Cf,
//                       [1024,1536): tanh(+bias2) -> Cf2); stride 512 each.
template <int BM, int BN, int THREADS, int MODE>
__global__ void __launch_bounds__(THREADS, 1)
mgemm(const bf16* __restrict__ Ah, const bf16* __restrict__ Al,
      const bf16* __restrict__ Bh, const bf16* __restrict__ Bl,
      int Kd, int Nc,
      float* __restrict__ Cf, float* __restrict__ Cf2,
      bf16* __restrict__ Chi, bf16* __restrict__ Clo,
      const float* __restrict__ bias, const float* __restrict__ bias2, float scale)
{
    constexpr int NWARPS = THREADS / 32;
    constexpr int NWN = (BN == 256) ? 4 : 2;
    constexpr int NWM = NWARPS / NWN;
    constexpr int WM = BM / NWM;      // 32
    constexpr int MF = WM / 16;       // 2
    constexpr int NF = BN / (NWN * 8);  // 8 or 4
    constexpr int APL = BM * 128;
    constexpr int BPL = BN * 128;
    constexpr int STAGE = 2 * APL + 2 * BPL;
    constexpr int SEGS = (2 * BM + 2 * BN) * 8;
    constexpr int SPT = SEGS / THREADS;

    extern __shared__ char smem_raw[];
    uint32_t sb0 = smem_u32(smem_raw);

    int tid = threadIdx.x, w = tid >> 5, lane = tid & 31;
    int row0 = blockIdx.y * BM, col0 = blockIdx.x * BN;
    int wm0 = (w / NWN) * WM, wn0 = (w % NWN) * (BN / NWN);
    int nch = Kd >> 6;

    float acc[MF][NF][4];
#pragma unroll
    for (int i = 0; i < MF; i++)
#pragma unroll
        for (int j = 0; j < NF; j++)
#pragma unroll
            for (int u = 0; u < 4; u++) acc[i][j][u] = 0.f;

    auto issue = [&](int c) {
        uint32_t sbase = sb0 + (c & 1) * STAGE;
        int k0 = c << 6;
#pragma unroll
        for (int i = 0; i < SPT; i++) {
            int sg = i * THREADS + tid;
            int rr = sg >> 3, q = sg & 7;
            const bf16* srcp;
            uint32_t dstb;
            int lr;
            if (rr < 2 * BM) {
                int pl = rr >= BM;
                lr = rr - pl * BM;
                srcp = (pl ? Al : Ah) + (size_t)(row0 + lr) * Kd + k0 + q * 8;
                dstb = sbase + pl * APL;
            } else {
                int rr2 = rr - 2 * BM;
                int pl = rr2 >= BN;
                lr = rr2 - pl * BN;
                srcp = (pl ? Bl : Bh) + (size_t)(col0 + lr) * Kd + k0 + q * 8;
                dstb = sbase + 2 * APL + pl * BPL;
            }
            uint32_t off = (uint32_t)(lr * 128 + q * 16);
            off ^= (off >> 3) & 0x70;
            cp16(dstb + off, (const void*)srcp);
        }
        asm volatile("cp.async.commit_group;");
    };

    issue(0);
    for (int c = 0; c < nch; c++) {
        if (c + 1 < nch) {
            issue(c + 1);
            asm volatile("cp.async.wait_group 1;");
        } else {
            asm volatile("cp.async.wait_group 0;");
        }
        __syncthreads();

        uint32_t sA = sb0 + (c & 1) * STAGE;
        uint32_t sAl = sA + APL, sBh = sA + 2 * APL, sBl = sBh + BPL;
#pragma unroll
        for (int ks = 0; ks < 4; ks++) {
            uint32_t ah[MF][4], al_[MF][4];
#pragma unroll
            for (int i = 0; i < MF; i++) {
                uint32_t off = (uint32_t)((wm0 + i * 16 + (lane & 15)) * 128 +
                                          ks * 32 + ((lane >> 4) << 4));
                off ^= (off >> 3) & 0x70;
                ldsm4(ah[i], sA + off);
                ldsm4(al_[i], sAl + off);
            }
            uint32_t b[NF][2];
#pragma unroll
            for (int j2 = 0; j2 < NF / 2; j2++) {
                uint32_t off = (uint32_t)((wn0 + j2 * 16 + (lane & 7) + ((lane >> 4) << 3)) * 128 +
                                          ks * 32 + (((lane >> 3) & 1) << 4));
                off ^= (off >> 3) & 0x70;
                uint32_t t[4];
                ldsm4(t, sBh + off);
                b[2 * j2][0] = t[0]; b[2 * j2][1] = t[1];
                b[2 * j2 + 1][0] = t[2]; b[2 * j2 + 1][1] = t[3];
            }
#pragma unroll
            for (int i = 0; i < MF; i++)
#pragma unroll
                for (int j = 0; j < NF; j++) hmma(acc[i][j], ah[i], b[j]);
#pragma unroll
            for (int i = 0; i < MF; i++)
#pragma unroll
                for (int j = 0; j < NF; j++) hmma(acc[i][j], al_[i], b[j]);
#pragma unroll
            for (int j2 = 0; j2 < NF / 2; j2++) {
                uint32_t off = (uint32_t)((wn0 + j2 * 16 + (lane & 7) + ((lane >> 4) << 3)) * 128 +
                                          ks * 32 + (((lane >> 3) & 1) << 4));
                off ^= (off >> 3) & 0x70;
                uint32_t t[4];
                ldsm4(t, sBl + off);
                b[2 * j2][0] = t[0]; b[2 * j2][1] = t[1];
                b[2 * j2 + 1][0] = t[2]; b[2 * j2 + 1][1] = t[3];
            }
#pragma unroll
            for (int i = 0; i < MF; i++)
#pragma unroll
                for (int j = 0; j < NF; j++) hmma(acc[i][j], ah[i], b[j]);
        }
        __syncthreads();
    }

    // ---- epilogue ----
    int seg = col0 >> 9;  // for MODE 5 (uniform per CTA since BN=256 | 512)
#pragma unroll
    for (int i = 0; i < MF; i++) {
#pragma unroll
        for (int j = 0; j < NF; j++) {
            int r = row0 + wm0 + i * 16 + (lane >> 2);
            int cp = col0 + wn0 + j * 8 + ((lane & 3) << 1);
#pragma unroll
            for (int half = 0; half < 2; half++) {
                int rr = r + half * 8;
                float x0 = acc[i][j][half * 2 + 0];
                float x1 = acc[i][j][half * 2 + 1];
                if (MODE == 4) {
                    bf16 h0, l0, h1, l1;
                    split2(x0, h0, l0);
                    split2(x1, h1, l1);
                    __nv_bfloat162 ph; ph.x = h0; ph.y = h1;
                    __nv_bfloat162 pl2; pl2.x = l0; pl2.y = l1;
                    *reinterpret_cast<__nv_bfloat162*>(&Chi[(size_t)rr * Nc + cp]) = ph;
                    *reinterpret_cast<__nv_bfloat162*>(&Clo[(size_t)rr * Nc + cp]) = pl2;
                } else if (MODE == 5) {
                    int colL = cp - seg * 512;
                    if (seg == 0) {
                        bf16 h0, l0, h1, l1;
                        split2(x0, h0, l0);
                        split2(x1, h1, l1);
                        __nv_bfloat162 ph; ph.x = h0; ph.y = h1;
                        __nv_bfloat162 pl2; pl2.x = l0; pl2.y = l1;
                        *reinterpret_cast<__nv_bfloat162*>(&Chi[(size_t)rr * Ss + colL]) = ph;
                        *reinterpret_cast<__nv_bfloat162*>(&Clo[(size_t)rr * Ss + colL]) = pl2;
                    } else if (seg == 1) {
                        float2 o;
                        o.x = 1.f / (1.f + __expf(-(x0 + bias[colL])));
                        o.y = 1.f / (1.f + __expf(-(x1 + bias[colL + 1])));
                        *reinterpret_cast<float2*>(&Cf[(size_t)rr * Ss + colL]) = o;
                    } else {
                        float2 o;
                        o.x = tanhf(x0 + bias2[colL]);
                        o.y = tanhf(x1 + bias2[colL + 1]);
                        *reinterpret_cast<float2*>(&Cf2[(size_t)rr * Ss + colL]) = o;
                    }
                } else {
                    if (MODE == 1) { x0 *= scale; x1 *= scale; }
                    float2 o; o.x = x0; o.y = x1;
                    *reinterpret_cast<float2*>(&Cf[(size_t)rr * Nc + cp]) = o;
                }
            }
        }
    }
}

// ======================= prep / elementwise kernels ==========================
__global__ void convert_split_kernel(const float* __restrict__ in,
                                     bf16* __restrict__ oh, bf16* __restrict__ ol,
                                     size_t n4) {
    size_t i = (size_t)blockIdx.x * blockDim.x + threadIdx.x;
    if (i >= n4) return;
    float4 v = reinterpret_cast<const float4*>(in)[i];
    bf16 h0, l0, h1, l1, h2, l2, h3, l3;
    split2(v.x, h0, l0); split2(v.y, h1, l1); split2(v.z, h2, l2); split2(v.w, h3, l3);
    __nv_bfloat162 a, b, c, d;
    a.x = h0; a.y = h1; b.x = h2; b.y = h3;
    c.x = l0; c.y = l1; d.x = l2; d.y = l3;
    reinterpret_cast<__nv_bfloat162*>(oh)[i * 2] = a;
    reinterpret_cast<__nv_bfloat162*>(oh)[i * 2 + 1] = b;
    reinterpret_cast<__nv_bfloat162*>(ol)[i * 2] = c;
    reinterpret_cast<__nv_bfloat162*>(ol)[i * 2 + 1] = d;
}

__global__ void transpose_split_kernel(const float* __restrict__ W,
                                       bf16* __restrict__ Th, bf16* __restrict__ Tl,
                                       int R, int C) {
    __shared__ float t[32][33];
    int c0 = blockIdx.x * 32, r0 = blockIdx.y * 32;
    int tx = threadIdx.x, ty = threadIdx.y;
#pragma unroll
    for (int i = 0; i < 32; i += 8)
        t[ty + i][tx] = W[(size_t)(r0 + ty + i) * C + c0 + tx];
    __syncthreads();
#pragma unroll
    for (int i = 0; i < 32; i += 8) {
        float v = t[tx][ty + i];
        bf16 h, l;
        split2(v, h, l);
        size_t idx = (size_t)(c0 + ty + i) * R + r0 + tx;
        Th[idx] = h;
        Tl[idx] = l;
    }
}

__global__ void kv_kernel(const float* __restrict__ state,
                          const float* __restrict__ Wk,
                          const float* __restrict__ Wv) {
    int j = blockIdx.x;
    __shared__ float srow[Ss];
    for (int c = threadIdx.x; c < Ss; c += blockDim.x) srow[c] = state[j * Ss + c];
    __syncthreads();
    for (int c = threadIdx.x; c < Ss; c += blockDim.x) {
        float ak = 0.f, av = 0.f;
        for (int t = 0; t < Ss; t++) {
            float s = srow[t];
            ak += s * Wk[t * Ss + c];
            av += s * Wv[t * Ss + c];
        }
        bf16 h, l;
        split2(ak, h, l);
        g_kp[0][j * Ss + c] = h; g_kp[1][j * Ss + c] = l;
        split2(av, h, l);
        g_vT[0][c * Kslots + j] = h; g_vT[1][c * Kslots + j] = l;
        split2(srow[c], h, l);
        g_st[0][j * Ss + c] = h; g_st[1][j * Ss + c] = l;
    }
}

template <bool SPLIT_OUT>
__global__ void softmax_kernel(const float* __restrict__ logits,
                               const float* __restrict__ gate,
                               bf16* __restrict__ oh, bf16* __restrict__ ol,
                               float* __restrict__ of) {
    int row = blockIdx.x * blockDim.y + threadIdx.y;
    int lane = threadIdx.x;
    float v0 = logits[(size_t)row * 64 + lane];
    float v1 = logits[(size_t)row * 64 + 32 + lane];
    float m = fmaxf(v0, v1);
#pragma unroll
    for (int o = 16; o; o >>= 1) m = fmaxf(m, __shfl_xor_sync(0xffffffffu, m, o));
    float e0 = __expf(v0 - m), e1 = __expf(v1 - m);
    float s = e0 + e1;
#pragma unroll
    for (int o = 16; o; o >>= 1) s += __shfl_xor_sync(0xffffffffu, s, o);
    float inv = 1.f / s;
    if (!SPLIT_OUT) inv *= gate[row];
    float a0 = e0 * inv, a1 = e1 * inv;
    if (SPLIT_OUT) {
        bf16 h, l;
        split2(a0, h, l);
        oh[(size_t)row * 64 + lane] = h; ol[(size_t)row * 64 + lane] = l;
        split2(a1, h, l);
        oh[(size_t)row * 64 + 32 + lane] = h; ol[(size_t)row * 64 + 32 + lane] = l;
    } else {
        of[(size_t)row * 64 + lane] = a0;
        of[(size_t)row * 64 + 32 + lane] = a1;
    }
}

__global__ void ln_gate_kernel(const float* __restrict__ nf,
                               const float* __restrict__ ro,
                               const float* __restrict__ gamma,
                               const float* __restrict__ beta,
                               const float* __restrict__ Wg,
                               const float* __restrict__ bg,
                               float* __restrict__ h,
                               bf16* __restrict__ hh, bf16* __restrict__ hl,
                               float* __restrict__ gate) {
    int row = blockIdx.x;
    int tid = threadIdx.x;
    __shared__ float sh[16];
    float4 a = reinterpret_cast<const float4*>(nf + (size_t)row * Dd)[tid];
    float4 b = reinterpret_cast<const float4*>(ro + (size_t)row * Dd)[tid];
    float v0 = a.x + b.x, v1 = a.y + b.y, v2 = a.z + b.z, v3 = a.w + b.w;
    float s = v0 + v1 + v2 + v3;
    float sq = v0 * v0 + v1 * v1 + v2 * v2 + v3 * v3;
    int lane = tid & 31, wid = tid >> 5;
#pragma unroll
    for (int o = 16; o; o >>= 1) {
        s += __shfl_xor_sync(0xffffffffu, s, o);
        sq += __shfl_xor_sync(0xffffffffu, sq, o);
    }
    if (lane == 0) { sh[wid] = s; sh[8 + wid] = sq; }
    __syncthreads();
    if (tid < 32) {
        float rs = (lane < 8) ? sh[lane] : 0.f;
        float rq = (lane < 8) ? sh[8 + lane] : 0.f;
#pragma unroll
        for (int o = 4; o; o >>= 1) {
            rs += __shfl_xor_sync(0xffffffffu, rs, o);
            rq += __shfl_xor_sync(0xffffffffu, rq, o);
        }
        if (lane == 0) { sh[0] = rs; sh[1] = rq; }
    }
    __syncthreads();
    float mu = sh[0] * (1.f / Dd);
    float var = sh[1] * (1.f / Dd) - mu * mu;
    float inv = rsqrtf(var + 1e-6f);
    __syncthreads();

    float4 g4 = reinterpret_cast<const float4*>(gamma)[tid];
    float4 b4 = reinterpret_cast<const float4*>(beta)[tid];
    float h0 = (v0 - mu) * inv * g4.x + b4.x;
    float h1 = (v1 - mu) * inv * g4.y + b4.y;
    float h2 = (v2 - mu) * inv * g4.z + b4.z;
    float h3 = (v3 - mu) * inv * g4.w + b4.w;
    float4 o4; o4.x = h0; o4.y = h1; o4.z = h2; o4.w = h3;
    reinterpret_cast<float4*>(h + (size_t)row * Dd)[tid] = o4;

    bf16 th0, tl0, th1, tl1, th2, tl2, th3, tl3;
    split2(h0, th0, tl0); split2(h1, th1, tl1);
    split2(h2, th2, tl2); split2(h3, th3, tl3);
    __nv_bfloat162 p0, p1, q0, q1;
    p0.x = th0; p0.y = th1; p1.x = th2; p1.y = th3;
    q0.x = tl0; q0.y = tl1; q1.x = tl2; q1.y = tl3;
    reinterpret_cast<__nv_bfloat162*>(hh + (size_t)row * Dd)[tid * 2] = p0;
    reinterpret_cast<__nv_bfloat162*>(hh + (size_t)row * Dd)[tid * 2 + 1] = p1;
    reinterpret_cast<__nv_bfloat162*>(hl + (size_t)row * Dd)[tid * 2] = q0;
    reinterpret_cast<__nv_bfloat162*>(hl + (size_t)row * Dd)[tid * 2 + 1] = q1;

    float4 w4 = reinterpret_cast<const float4*>(Wg)[tid];
    float gd = h0 * w4.x + h1 * w4.y + h2 * w4.z + h3 * w4.w;
#pragma unroll
    for (int o = 16; o; o >>= 1) gd += __shfl_xor_sync(0xffffffffu, gd, o);
    if (lane == 0) sh[wid] = gd;
    __syncthreads();
    if (tid == 0) {
        float t = 0.f;
#pragma unroll
        for (int wv = 0; wv < 8; wv++) t += sh[wv];
        gate[row] = 1.f / (1.f + __expf(-(t + bg[0])));
    }
}

__global__ void __launch_bounds__(512)
aggregate_kernel(const float* __restrict__ w, const float* __restrict__ vec,
                 float* __restrict__ part) {
    int blk = blockIdx.x;
    int tid = threadIdx.x;
    int j = tid >> 3;
    int sb = tid & 7;
    float acc[64];
#pragma unroll
    for (int t = 0; t < 64; t++) acc[t] = 0.f;
    __shared__ float ws[64];
    __shared__ float vs[Ss];
    int r0 = blk * AGG_ROWS;
    for (int r = 0; r < AGG_ROWS; r++) {
        size_t row = r0 + r;
        __syncthreads();
        if (tid < 64) ws[tid] = w[row * 64 + tid];
        if (tid < 512) vs[tid] = vec[row * Ss + tid];
        __syncthreads();
        float wv = ws[j];
#pragma unroll
        for (int t = 0; t < 64; t++) acc[t] += wv * vs[sb + 8 * t];
    }
    float* p = part + (size_t)blk * (Kslots * Ss) + j * Ss;
#pragma unroll
    for (int t = 0; t < 64; t++) p[sb + 8 * t] = acc[t];
}

__global__ void finalize_kernel(const float* __restrict__ state, float* __restrict__ out) {
    int e = blockIdx.x * blockDim.x + threadIdx.x;
    if (e >= Kslots * Ss) return;
    float se = 0.f, sw = 0.f;
    for (int r = 0; r < AGG_BLOCKS; r++) {
        se += g_partE[(size_t)r * (Kslots * Ss) + e];
        sw += g_partW[(size_t)r * (Kslots * Ss) + e];
    }
    float ea = fminf(fmaxf(se, 0.f), 1.f);
    out[e] = state[e] * (1.f - ea) + sw;
}

// ======================= launcher ============================================
extern "C" void kernel_launch(void* const* d_in, const int* in_sizes, int n_in,
                              void* d_out, int out_size) {
    const float* nf    = (const float*)d_in[0];
    const float* state = (const float*)d_in[1];
    const float* Wq    = (const float*)d_in[2];
    const float* Wk    = (const float*)d_in[3];
    const float* Wv    = (const float*)d_in[4];
    const float* Wo    = (const float*)d_in[5];
    const float* gam   = (const float*)d_in[6];
    const float* bet   = (const float*)d_in[7];
    const float* Wa    = (const float*)d_in[8];
    const float* Wg    = (const float*)d_in[9];
    const float* bg    = (const float*)d_in[10];
    const float* We    = (const float*)d_in[11];
    const float* be    = (const float*)d_in[12];
    const float* Wc    = (const float*)d_in[13];
    const float* bc    = (const float*)d_in[14];

    float* h_out  = (float*)d_out;
    float* ns_out = (float*)d_out + (size_t)Nn * Dd;

    auto sym = [](const void* s) {
        void* p = nullptr;
        cudaGetSymbolAddress(&p, s);
        return p;
    };
    bf16* xh  = (bf16*)sym(g_xh);
    bf16* xl  = (bf16*)sym(g_xl);
    bf16* qh  = (bf16*)sym(g_qh);
    bf16* ql  = (bf16*)sym(g_ql);
    bf16* ath = (bf16*)sym(g_ath);
    bf16* atl = (bf16*)sym(g_atl);
    bf16* rh  = (bf16*)sym(g_rh);
    bf16* rl  = (bf16*)sym(g_rl);
    bf16* hh  = (bf16*)sym(g_hh);
    bf16* hl  = (bf16*)sym(g_hl);
    float* ro    = (float*)sym(g_ro);
    float* logit = (float*)sym(g_logits);
    float* ers   = (float*)sym(g_erase);
    float* cnt   = (float*)sym(g_content);
    float* wtd   = (float*)sym(g_weighted);
    float* gate  = (float*)sym(g_gate);
    float* pE    = (float*)sym(g_partE);
    float* pW    = (float*)sym(g_partW);
    bf16* wqT  = (bf16*)sym(g_wqT);
    bf16* woT  = (bf16*)sym(g_woT);
    bf16* wall = (bf16*)sym(g_wall);
    bf16* kp   = (bf16*)sym(g_kp);
    bf16* vT   = (bf16*)sym(g_vT);
    bf16* st   = (bf16*)sym(g_st);
    const size_t SD   = (size_t)Ss * Dd;
    const size_t DS   = (size_t)Dd * Ss;
    const size_t KS   = (size_t)Kslots * Ss;
    const size_t SK   = (size_t)Ss * Kslots;
    const size_t WALL = (size_t)(3 * Ss) * Dd;

    const int SM_BIG   = 2 * (2 * 128 * 128 + 2 * 256 * 128);  // 196608
    const int SM_SMALL = 2 * (2 * 128 * 128 + 2 * 64 * 128);   //  98304
    cudaFuncSetAttribute(mgemm<128, 256, 512, 0>, cudaFuncAttributeMaxDynamicSharedMemorySize, SM_BIG);
    cudaFuncSetAttribute(mgemm<128, 256, 512, 4>, cudaFuncAttributeMaxDynamicSharedMemorySize, SM_BIG);
    cudaFuncSetAttribute(mgemm<128, 256, 512, 5>, cudaFuncAttributeMaxDynamicSharedMemorySize, SM_BIG);
    cudaFuncSetAttribute(mgemm<128, 64, 256, 0>, cudaFuncAttributeMaxDynamicSharedMemorySize, SM_SMALL);
    cudaFuncSetAttribute(mgemm<128, 64, 256, 1>, cudaFuncAttributeMaxDynamicSharedMemorySize, SM_SMALL);

    const float scale = 0.044194173824159216f;  // 1/sqrt(512)

    // ---- prep ----
    convert_split_kernel<<<(Nn * (Dd / 4)) / 256, 256>>>(nf, xh, xl, (size_t)Nn * Dd / 4);
    transpose_split_kernel<<<dim3(Ss / 32, Dd / 32), dim3(32, 8)>>>(Wq, wqT, wqT + SD, Dd, Ss);
    transpose_split_kernel<<<dim3(Dd / 32, Ss / 32), dim3(32, 8)>>>(Wo, woT, woT + DS, Ss, Dd);
    transpose_split_kernel<<<dim3(Ss / 32, Dd / 32), dim3(32, 8)>>>(
        Wa, wall, wall + WALL, Dd, Ss);
    transpose_split_kernel<<<dim3(Ss / 32, Dd / 32), dim3(32, 8)>>>(
        We, wall + SD, wall + WALL + SD, Dd, Ss);
    transpose_split_kernel<<<dim3(Ss / 32, Dd / 32), dim3(32, 8)>>>(
        Wc, wall + 2 * SD, wall + WALL + 2 * SD, Dd, Ss);
    kv_kernel<<<Kslots, 256>>>(state, Wk, Wv);

    // ---- read path ----
    mgemm<128, 256, 512, 4><<<dim3(2, 512), 512, SM_BIG>>>(
        xh, xl, wqT, wqT + SD, Dd, Ss,
        nullptr, nullptr, qh, ql, nullptr, nullptr, 0.f);
    mgemm<128, 64, 256, 1><<<dim3(1, 512), 256, SM_SMALL>>>(
        qh, ql, kp, kp + KS, Ss, 64,
        logit, nullptr, nullptr, nullptr, nullptr, nullptr, scale);
    softmax_kernel<true><<<Nn / 8, dim3(32, 8)>>>(logit, nullptr, ath, atl, nullptr);
    mgemm<128, 256, 512, 4><<<dim3(2, 512), 512, SM_BIG>>>(
        ath, atl, vT, vT + SK, Kslots, Ss,
        nullptr, nullptr, rh, rl, nullptr, nullptr, 0.f);
    mgemm<128, 256, 512, 0><<<dim3(4, 512), 512, SM_BIG>>>(
        rh, rl, woT, woT + DS, Ss, Dd,
        ro, nullptr, nullptr, nullptr, nullptr, nullptr, 0.f);
    ln_gate_kernel<<<Nn, 256>>>(nf, ro, gam, bet, Wg, bg, h_out, hh, hl, gate);

    // ---- write path: fused h@[Wa|We|Wc] ----
    mgemm<128, 256, 512, 5><<<dim3(6, 512), 512, SM_BIG>>>(
        hh, hl, wall, wall + WALL, Dd, 3 * Ss,
        ers, cnt, qh, ql, be, bc, 0.f);
    mgemm<128, 64, 256, 0><<<dim3(1, 512), 256, SM_SMALL>>>(
        qh, ql, st, st + KS, Ss, 64,
        logit, nullptr, nullptr, nullptr, nullptr, nullptr, 0.f);
    softmax_kernel<false><<<Nn / 8, dim3(32, 8)>>>(logit, gate, nullptr, nullptr, wtd);
    aggregate_kernel<<<AGG_BLOCKS, 512>>>(wtd, ers, pE);
    aggregate_kernel<<<AGG_BLOCKS, 512>>>(wtd, cnt, pW);
    finalize_kernel<<<(Kslots * Ss + 255) / 256, 256>>>(state, ns_out);
}